// round 4
// baseline (speedup 1.0000x reference)
#include <cuda_runtime.h>
#include <cuda_bf16.h>

// Problem shapes (fixed by reference setup_inputs)
#define B    4
#define CIN  512
#define OUT  256
#define NN   4096

#define GRID 1024       // == B*OUT; also 2 input rows per block (2048 rows)
#define TPB  128

// Scratch + barrier state (zero-init, no cudaMalloc)
__device__ float    g_X[B * CIN];
__device__ unsigned g_count = 0;
__device__ unsigned g_sense = 0;

// Single fused kernel:
//   phase 1: row-sums of x  -> g_X            (2 rows per block)
//   grid barrier (sense-reversal, replay-safe)
//   phase 2: E = elu(dot(W1[o], X[b])), broadcast over N -> out
__global__ __launch_bounds__(TPB, 7) void k_fused(const float* __restrict__ x,
                                                  const float* __restrict__ W1,
                                                  float* __restrict__ out) {
    const int t   = threadIdx.x;
    const int blk = blockIdx.x;
    const int w   = t >> 5;
    const int l   = t & 31;

    // Capture barrier sense BEFORE doing any work (no block can flip it until
    // this block arrives, so this read is race-free).
    const unsigned sense0 = *(volatile unsigned*)&g_sense;

    // Prefetch phase-2 W1 row now — independent of phase 1, latency hides
    // behind the row-sum work + barrier wait.
    const int bo = blk;
    const int b  = bo >> 8;          // OUT = 256
    const int o  = bo & 255;
    const float4 w4 =
        reinterpret_cast<const float4*>(W1 + (size_t)o * CIN)[t];

    // ---------------- phase 1: two 16 KB rows per block ----------------
    float rs0, rs1;
    {
        const float4* __restrict__ p0 =
            reinterpret_cast<const float4*>(x + (size_t)(2 * blk + 0) * NN);
        const float4* __restrict__ p1 =
            reinterpret_cast<const float4*>(x + (size_t)(2 * blk + 1) * NN);
        float4 v[8];
        #pragma unroll
        for (int i = 0; i < 8; i++) v[i] = p0[t + i * TPB];
        float a = 0.f;
        #pragma unroll
        for (int i = 0; i < 8; i++) a += (v[i].x + v[i].y) + (v[i].z + v[i].w);
        rs0 = a;
        #pragma unroll
        for (int i = 0; i < 8; i++) v[i] = p1[t + i * TPB];
        a = 0.f;
        #pragma unroll
        for (int i = 0; i < 8; i++) a += (v[i].x + v[i].y) + (v[i].z + v[i].w);
        rs1 = a;
    }
    #pragma unroll
    for (int off = 16; off > 0; off >>= 1) {
        rs0 += __shfl_down_sync(0xffffffffu, rs0, off);
        rs1 += __shfl_down_sync(0xffffffffu, rs1, off);
    }
    __shared__ float sm[2][4];
    if (l == 0) { sm[0][w] = rs0; sm[1][w] = rs1; }
    __syncthreads();
    if (t < 2)
        g_X[2 * blk + t] = (sm[t][0] + sm[t][1]) + (sm[t][2] + sm[t][3]);
    __threadfence();          // writers (t<2) publish g_X before arrival below
    __syncthreads();          // t==0 arrives only after writers' fence

    // ---------------- grid barrier (sense reversal) ----------------
    if (t == 0) {
        const unsigned prev = atomicAdd(&g_count, 1u);
        if (prev == GRID - 1) {
            g_count = 0;                       // reset for next graph replay
            __threadfence();
            *(volatile unsigned*)&g_sense = sense0 ^ 1u;
        } else {
            while (*(volatile unsigned*)&g_sense == sense0) { }
        }
        __threadfence();
    }
    __syncthreads();

    // ---------------- phase 2: dot + elu + broadcast ----------------
    // g_X read bypasses L1 (first-read anyway; .cg for cross-SM safety).
    const float4 xv4 =
        __ldcg(reinterpret_cast<const float4*>(g_X + b * CIN) + t);
    float s = fmaf(w4.x, xv4.x,
              fmaf(w4.y, xv4.y,
              fmaf(w4.z, xv4.z, w4.w * xv4.w)));
    #pragma unroll
    for (int off = 16; off > 0; off >>= 1)
        s += __shfl_down_sync(0xffffffffu, s, off);

    __shared__ float sd[4];
    __shared__ float ev;
    if (l == 0) sd[w] = s;
    __syncthreads();
    if (t == 0) {
        const float u = (sd[0] + sd[1]) + (sd[2] + sd[3]);
        ev = (u > 0.f) ? u : expm1f(u);        // elu, alpha=1
    }
    __syncthreads();

    const float  v  = ev;
    const float4 v4 = make_float4(v, v, v, v);
    float4* __restrict__ q = reinterpret_cast<float4*>(out + (size_t)bo * NN);
    #pragma unroll
    for (int i = 0; i < 8; i++)                // 1024 float4 / 128 threads
        q[t + i * TPB] = v4;
}

extern "C" void kernel_launch(void* const* d_in, const int* in_sizes, int n_in,
                              void* d_out, int out_size) {
    const float* x  = (const float*)d_in[0];   // [B, CIN, 1, NN]
    const float* W1 = (const float*)d_in[1];   // [OUT, CIN]
    // d_in[2] = w2, d_in[3] = bias_mat: unused (softmax over size-1 axis == 1)
    float* out = (float*)d_out;                // [B, OUT, 1, NN]

    k_fused<<<GRID, TPB>>>(x, W1, out);
}

// round 5
// speedup vs baseline: 1.1895x; 1.1895x over previous
#include <cuda_runtime.h>
#include <cuda_bf16.h>

// Problem shapes (fixed by reference setup_inputs)
#define B    4
#define CIN  512
#define OUT  256
#define NN   4096

// Scratch (no cudaMalloc allowed)
__device__ float g_X[B * CIN];   // X[b,c] = sum_n x[b,c,n]

// ---------------------------------------------------------------------------
// Kernel 1: reduce x over N. One block per row, 128 threads, 8 float4 each,
// front-batched for MLP=8 per thread.
// ---------------------------------------------------------------------------
__global__ __launch_bounds__(128) void k_rowsum(const float* __restrict__ x) {
    const int row = blockIdx.x;                 // 0 .. B*CIN-1
    const float4* __restrict__ p =
        reinterpret_cast<const float4*>(x + (size_t)row * NN);
    const int t = threadIdx.x;

    float4 v[8];
    #pragma unroll
    for (int i = 0; i < 8; i++) v[i] = p[t + i * 128];

    float s = 0.f;
    #pragma unroll
    for (int i = 0; i < 8; i++) s += (v[i].x + v[i].y) + (v[i].z + v[i].w);

    #pragma unroll
    for (int off = 16; off > 0; off >>= 1)
        s += __shfl_down_sync(0xffffffffu, s, off);

    __shared__ float sm[4];
    if ((t & 31) == 0) sm[t >> 5] = s;
    __syncthreads();
    if (t == 0)
        g_X[row] = (sm[0] + sm[1]) + (sm[2] + sm[3]);
}

// ---------------------------------------------------------------------------
// Kernel 2: 256 blocks x 256 threads, 4 output rows per block.
// Warps 0-3: in-warp 512-dot + elu for one row each (no cross-warp reduce).
// One syncthreads, then all 8 warps stream 64 KB of dependency-free stores.
// ---------------------------------------------------------------------------
__global__ __launch_bounds__(256) void k_out2(const float* __restrict__ W1,
                                              float* __restrict__ out) {
    const int t    = threadIdx.x;
    const int warp = t >> 5;
    const int lane = t & 31;

    __shared__ float ev[4];

    if (warp < 4) {
        const int bo = blockIdx.x * 4 + warp;   // 0 .. 1023
        const int b  = bo >> 8;                 // OUT = 256
        const int o  = bo & 255;
        const float4* __restrict__ wr =
            reinterpret_cast<const float4*>(W1 + (size_t)o * CIN);
        const float4* __restrict__ xr =
            reinterpret_cast<const float4*>(g_X + (size_t)b * CIN);

        // batch all 8 loads (4 W1 + 4 X) before the FMAs
        float4 a0 = wr[lane];       float4 a1 = wr[lane + 32];
        float4 a2 = wr[lane + 64];  float4 a3 = wr[lane + 96];
        float4 b0 = xr[lane];       float4 b1 = xr[lane + 32];
        float4 b2 = xr[lane + 64];  float4 b3 = xr[lane + 96];

        float s0 = fmaf(a0.x, b0.x, fmaf(a0.y, b0.y, fmaf(a0.z, b0.z, a0.w * b0.w)));
        float s1 = fmaf(a1.x, b1.x, fmaf(a1.y, b1.y, fmaf(a1.z, b1.z, a1.w * b1.w)));
        float s2 = fmaf(a2.x, b2.x, fmaf(a2.y, b2.y, fmaf(a2.z, b2.z, a2.w * b2.w)));
        float s3 = fmaf(a3.x, b3.x, fmaf(a3.y, b3.y, fmaf(a3.z, b3.z, a3.w * b3.w)));
        float s  = (s0 + s1) + (s2 + s3);

        #pragma unroll
        for (int off = 16; off > 0; off >>= 1)
            s += __shfl_down_sync(0xffffffffu, s, off);

        if (lane == 0)
            ev[warp] = (s > 0.f) ? s : expm1f(s);   // elu, alpha=1
    }
    __syncthreads();

    const float e0 = ev[0], e1 = ev[1], e2 = ev[2], e3 = ev[3];
    float4* __restrict__ q =
        reinterpret_cast<float4*>(out) + (size_t)blockIdx.x * 4096;

    const float4 v0 = make_float4(e0, e0, e0, e0);
    const float4 v1 = make_float4(e1, e1, e1, e1);
    const float4 v2 = make_float4(e2, e2, e2, e2);
    const float4 v3 = make_float4(e3, e3, e3, e3);

    // 4 rows x 1024 float4; 16 independent stores per thread, coalesced
    #pragma unroll
    for (int i = 0; i < 4; i++) q[t +    0 + i * 256] = v0;
    #pragma unroll
    for (int i = 0; i < 4; i++) q[t + 1024 + i * 256] = v1;
    #pragma unroll
    for (int i = 0; i < 4; i++) q[t + 2048 + i * 256] = v2;
    #pragma unroll
    for (int i = 0; i < 4; i++) q[t + 3072 + i * 256] = v3;
}

extern "C" void kernel_launch(void* const* d_in, const int* in_sizes, int n_in,
                              void* d_out, int out_size) {
    const float* x  = (const float*)d_in[0];   // [B, CIN, 1, NN]
    const float* W1 = (const float*)d_in[1];   // [OUT, CIN]
    // d_in[2] = w2, d_in[3] = bias_mat: unused (softmax over size-1 axis == 1)
    float* out = (float*)d_out;                // [B, OUT, 1, NN]

    k_rowsum<<<B * CIN, 128>>>(x);
    k_out2<<<OUT, 256>>>(W1, out);
}